// round 15
// baseline (speedup 1.0000x reference)
#include <cuda_runtime.h>
#include <cuda_fp16.h>
#include <cstdint>
#include <math.h>

// ============================================================================
// CustomAttention B=16, T=S=E=1024 fp32 -> FP16 tensor path.
// mma.sync m16n8k16 fp16->fp32, cp.async 4-stage BK=64(halves), ldmatrix,
// all GEMMs K-major (q/v projections store transposed).
// R15: 512-thread CTAs, block 128(M) x 256(N) x 64, 16 warps of 64x32,
// 1 CTA/SM (4 warps/SMSP). Cuts smem reads/MAC 25% -> tensor-bound.
// ============================================================================

#define ROWB 144                    // bytes per smem row (72 halves: 64 + 8 pad)
#define A_BYTES (128 * ROWB)        // 18432
#define B_OFF_BYTES A_BYTES
#define B_BYTES (256 * ROWB)        // 36864
#define STG_BYTES (A_BYTES + B_BYTES)   // 55296
#define SMEM_BYTES (4 * STG_BYTES)      // 221184

// ---------------- scratch (device globals; no allocation allowed) -----------
__device__ __half g_in[48u * 1024u * 1024u];  // fp16 query|key|value
__device__ __half g_rw[4u * 1024u * 1024u];   // fp16 Wq|Wk|Wv|Wo
__device__ float  g_bias[3 * 1024];           // bq|bk|bv (fp32)
__device__ __half g_q[16u * 1024u * 1024u];   // qT[i][b*1024+t]  (ld 16384)
__device__ __half g_k[16u * 1024u * 1024u];   // k[b*1024+s][t]   (ld 1024)
__device__ __half g_v[16u * 1024u * 1024u];   // vT[e][b*1024+s]  (ld 16384)
__device__ __half g_w[16u * 1024u * 1024u];
__device__ __half g_o[16u * 1024u * 1024u];

__device__ __forceinline__ void cpa16(uint32_t s, const __half* g) {
    asm volatile("cp.async.cg.shared.global [%0], [%1], 16;" :: "r"(s), "l"(g));
}
#define CP_COMMIT() asm volatile("cp.async.commit_group;")
#define CP_WAIT2()  asm volatile("cp.async.wait_group 2;")

__device__ __forceinline__ void ldsm4(uint32_t* r, uint32_t addr) {
    asm volatile("ldmatrix.sync.aligned.m8n8.x4.shared.b16 {%0,%1,%2,%3}, [%4];"
                 : "=r"(r[0]), "=r"(r[1]), "=r"(r[2]), "=r"(r[3]) : "r"(addr));
}
__device__ __forceinline__ void mma16(float* d, const uint32_t* a,
                                      uint32_t b0, uint32_t b1) {
    asm volatile(
        "mma.sync.aligned.m16n8k16.row.col.f32.f16.f16.f32 "
        "{%0,%1,%2,%3}, {%4,%5,%6,%7}, {%8,%9}, {%0,%1,%2,%3};"
        : "+f"(d[0]), "+f"(d[1]), "+f"(d[2]), "+f"(d[3])
        : "r"(a[0]), "r"(a[1]), "r"(a[2]), "r"(a[3]), "r"(b0), "r"(b1));
}

// ---------------- shared mainloop: 128x256 tile, K=1024 halves, K-major -----
// 512 threads: 16 warps, warp grid 2(M) x 8(N), warp tile 64x32.
#define LOAD_A(STGOFF, K16, AA)                                                \
    _Pragma("unroll") for (int mt = 0; mt < 4; mt++)                           \
        ldsm4(AA[mt], aLane + (STGOFF) + mt * (16 * ROWB) + (K16) * 32);

#define LOAD_B(STGOFF, K16, BB)                                                \
    _Pragma("unroll") for (int p = 0; p < 2; p++)                              \
        ldsm4(BB[p], bLane + (STGOFF) + p * (16 * ROWB) + (K16) * 32);

#define DO_MMAS(AA, BB)                                                        \
    _Pragma("unroll") for (int mt = 0; mt < 4; mt++)                           \
        _Pragma("unroll") for (int nt = 0; nt < 4; nt++)                       \
            mma16(acc[mt][nt], AA[mt], BB[nt >> 1][nt & 1],                    \
                  BB[nt >> 1][(nt & 1) + 2]);

// Tile body. Prefetch of stage KT+3 (slot PRE) spread across k16 sections:
// k16 0: B rows 0,64; k16 1: B rows 128,192; k16 2: A row 0; k16 3: A row 64.
#define KTILE(CUR, PRE, KT, DOPF)                                              \
    do {                                                                       \
        CP_WAIT2();                                                            \
        __syncthreads();                                                       \
        uint32_t a[4][4], b[2][2][4];                                          \
        LOAD_B((CUR) * STG_BYTES, 0, b[0])                                     \
        LOAD_A((CUR) * STG_BYTES, 0, a)                                        \
        _Pragma("unroll") for (int k16 = 0; k16 < 4; k16++) {                  \
            if (k16 < 3) { LOAD_B((CUR) * STG_BYTES, k16 + 1, b[(k16 + 1) & 1]) } \
            if (DOPF) {                                                        \
                const int k0 = ((KT) + 3) << 6;                                \
                const uint32_t st = (PRE) * STG_BYTES;                         \
                if (k16 == 0) {                                                \
                    cpa16(saB + st, gB + k0);                                  \
                    cpa16(saB + st + 64 * ROWB, gB + k0 + 64LL * sB);          \
                } else if (k16 == 1) {                                         \
                    cpa16(saB + st + 128 * ROWB, gB + k0 + 128LL * sB);        \
                    cpa16(saB + st + 192 * ROWB, gB + k0 + 192LL * sB);        \
                } else if (k16 == 2) {                                         \
                    cpa16(saA + st, gA + k0);                                  \
                } else {                                                       \
                    cpa16(saA + st + 64 * ROWB, gA + k0 + 64LL * sA);          \
                }                                                              \
            }                                                                  \
            if (k16 == 3) CP_COMMIT();                                         \
            DO_MMAS(a, b[k16 & 1])                                             \
            if (k16 < 3) { LOAD_A((CUR) * STG_BYTES, k16 + 1, a) }             \
        }                                                                      \
    } while (0)

__device__ __forceinline__ void gemm_main(const __half* __restrict__ At,
                                          const __half* __restrict__ Bt,
                                          int sA, int sB, char* smc,
                                          float (&acc)[4][4][4]) {
    const uint32_t smb = (uint32_t)__cvta_generic_to_shared(smc);
    const int tid = threadIdx.x, lane = tid & 31, warp = tid >> 5;
    const int wm = (warp & 1) << 6;        // 0 / 64
    const int wn = (warp >> 1) << 5;       // 0 .. 224

    // cp.async lanes: row = tid>>3 (+64*i), 16B chunk = (tid&7)*8 halves
    const int rq = tid >> 3, qh = (tid & 7) << 3;   // rq 0..63
    const __half* gA = At + (long long)rq * sA + qh;
    const __half* gB = Bt + (long long)rq * sB + qh;
    const uint32_t saA = smb + (uint32_t)(rq * ROWB + qh * 2);
    const uint32_t saB = smb + B_OFF_BYTES + (uint32_t)(rq * ROWB + qh * 2);

    // LDSM lane addressing (8x8 b16 matrices)
    const int seg = lane >> 3, li = lane & 7;
    const uint32_t aLane =
        smb + (uint32_t)((wm + ((seg & 1) << 3) + li) * ROWB + ((seg >> 1) << 4));
    const uint32_t bLane =
        smb + B_OFF_BYTES +
        (uint32_t)((wn + ((seg & 1) << 3) + li) * ROWB + ((seg >> 1) << 4));

    // prologue: stages 0,1,2 (tiles 0,1,2)
#pragma unroll
    for (int s = 0; s < 3; s++) {
        const uint32_t st = s * STG_BYTES;
        const int k0 = s << 6;
        cpa16(saA + st, gA + k0);
        cpa16(saA + st + 64 * ROWB, gA + k0 + 64LL * sA);
#pragma unroll
        for (int i = 0; i < 4; i++)
            cpa16(saB + st + i * (64 * ROWB), gB + k0 + i * 64LL * sB);
        CP_COMMIT();
    }

    // main: 16 k-tiles; prefetch valid for kt <= 12 (stage kt+3 <= 15)
#pragma unroll 1
    for (int kt = 0; kt < 12; kt += 4) {
        KTILE(0, 3, kt, true);
        KTILE(1, 0, kt + 1, true);
        KTILE(2, 1, kt + 2, true);
        KTILE(3, 2, kt + 3, true);
    }
    KTILE(0, 3, 12, true);
    KTILE(1, 0, 13, false);
    KTILE(2, 1, 14, false);
    KTILE(3, 2, 15, false);
}

// ---------------- standard GEMM: C[z][m][n] = scale*A.B^T (+bias) -----------
// HALFOUT: C is __half (rounded); else C is float with bias added.
template <bool BIAS, bool HALFOUT>
__global__ void __launch_bounds__(512, 1)
gemm_k(const __half* __restrict__ A, const __half* __restrict__ B,
       const float* __restrict__ bias, void* __restrict__ Cv,
       long long bsA, long long bsB, long long bsC,
       int sA, int sB, int ldC, float scale) {
    extern __shared__ char smc[];
    const int bn = blockIdx.x << 8, bm = blockIdx.y << 7, z = blockIdx.z;
    const __half* At = A + (long long)z * bsA + (long long)bm * sA;
    const __half* Bt = B + (long long)z * bsB + (long long)bn * sB;

    float acc[4][4][4];
#pragma unroll
    for (int i = 0; i < 4; i++)
#pragma unroll
        for (int j = 0; j < 4; j++)
#pragma unroll
            for (int l = 0; l < 4; l++) acc[i][j][l] = 0.f;

    gemm_main(At, Bt, sA, sB, smc, acc);

    const int lane = threadIdx.x & 31, warp = threadIdx.x >> 5;
    const int wm = (warp & 1) << 6, wn = (warp >> 1) << 5;
    const int gr = lane >> 2, kr = lane & 3;
#pragma unroll
    for (int mt = 0; mt < 4; mt++) {
        const long long r0 = (long long)(bm + wm + mt * 16 + gr) * ldC;
#pragma unroll
        for (int nt = 0; nt < 4; nt++) {
            const int col = bn + wn + nt * 8 + kr * 2;
            float b0 = 0.f, b1 = 0.f;
            if (BIAS) {
                float2 bb = *(const float2*)(bias + col);
                b0 = bb.x; b1 = bb.y;
            }
            float x0 = acc[mt][nt][0] * scale + b0;
            float x1 = acc[mt][nt][1] * scale + b1;
            float x2 = acc[mt][nt][2] * scale + b0;
            float x3 = acc[mt][nt][3] * scale + b1;
            if (HALFOUT) {
                __half* Cz = (__half*)Cv + (long long)z * bsC;
                *(__half2*)&Cz[r0 + col] = __floats2half2_rn(x0, x1);
                *(__half2*)&Cz[r0 + 8LL * ldC + col] = __floats2half2_rn(x2, x3);
            } else {
                float* Cz = (float*)Cv + (long long)z * bsC;
                *(float2*)&Cz[r0 + col] = make_float2(x0, x1);
                *(float2*)&Cz[r0 + 8LL * ldC + col] = make_float2(x2, x3);
            }
        }
    }
}

// ---------------- fused QKV projection: z=0 qT, z=1 k, z=2 vT ----------------
__global__ void __launch_bounds__(512, 1)
gemm_qkv(const __half* __restrict__ Ain, const __half* __restrict__ W,
         const float* __restrict__ biases,
         __half* __restrict__ Cq, __half* __restrict__ Ck,
         __half* __restrict__ Cv) {
    extern __shared__ char smc[];
    const int bn = blockIdx.x << 8, bm = blockIdx.y << 7, z = blockIdx.z;
    const __half* At = Ain + (long long)z * (16LL << 20) + (long long)bm * 1024;
    const __half* Bt = W + (long long)z * (1LL << 20) + (long long)bn * 1024;
    const float* bias = biases + z * 1024;

    float acc[4][4][4];
#pragma unroll
    for (int i = 0; i < 4; i++)
#pragma unroll
        for (int j = 0; j < 4; j++)
#pragma unroll
            for (int l = 0; l < 4; l++) acc[i][j][l] = 0.f;

    gemm_main(At, Bt, 1024, 1024, smc, acc);

    const int lane = threadIdx.x & 31, warp = threadIdx.x >> 5;
    const int wm = (warp & 1) << 6, wn = (warp >> 1) << 5;
    const int gr = lane >> 2, kr = lane & 3;

    if (z == 1) {  // normal store: k[m][n], ld 1024
#pragma unroll
        for (int mt = 0; mt < 4; mt++) {
            const long long r0 = (long long)(bm + wm + mt * 16 + gr) * 1024;
#pragma unroll
            for (int nt = 0; nt < 4; nt++) {
                const int col = bn + wn + nt * 8 + kr * 2;
                float2 bb = *(const float2*)(bias + col);
                *(__half2*)&Ck[r0 + col] =
                    __floats2half2_rn(acc[mt][nt][0] + bb.x, acc[mt][nt][1] + bb.y);
                *(__half2*)&Ck[r0 + 8LL * 1024 + col] =
                    __floats2half2_rn(acc[mt][nt][2] + bb.x, acc[mt][nt][3] + bb.y);
            }
        }
    } else {       // transposed store: CT[n][m], ld 16384
        __half* CT = (z == 0) ? Cq : Cv;
#pragma unroll
        for (int mt = 0; mt < 4; mt++) {
            const int row = bm + wm + mt * 16 + gr;
#pragma unroll
            for (int nt = 0; nt < 4; nt++) {
                const int col = bn + wn + nt * 8 + kr * 2;
                float2 bb = *(const float2*)(bias + col);
                CT[(long long)col * 16384 + row] = __float2half_rn(acc[mt][nt][0] + bb.x);
                CT[(long long)(col + 1) * 16384 + row] = __float2half_rn(acc[mt][nt][1] + bb.y);
                CT[(long long)col * 16384 + row + 8] = __float2half_rn(acc[mt][nt][2] + bb.x);
                CT[(long long)(col + 1) * 16384 + row + 8] = __float2half_rn(acc[mt][nt][3] + bb.y);
            }
        }
    }
}

// ---------------- prep: fp32 -> fp16 inputs + weights, copy biases ----------
__global__ void prep(const float* __restrict__ q, const float* __restrict__ k,
                     const float* __restrict__ v,
                     const float* __restrict__ w0, const float* __restrict__ w1,
                     const float* __restrict__ w2, const float* __restrict__ w3,
                     const float* __restrict__ b0, const float* __restrict__ b1,
                     const float* __restrict__ b2,
                     __half* __restrict__ hin, __half* __restrict__ hw,
                     float* __restrict__ bias) {
    const int b = blockIdx.x;
    if (b < 49152) {                       // 3 x 16M inputs
        const int t = b >> 14;
        const long long i = ((long long)(b & 16383) << 10) + (threadIdx.x << 2);
        const float* in = (t == 0) ? q : (t == 1) ? k : v;
        float4 x = *(const float4*)(in + i);
        __half* d = hin + (((long long)t) << 24) + i;
        *(__half2*)d = __floats2half2_rn(x.x, x.y);
        *(__half2*)(d + 2) = __floats2half2_rn(x.z, x.w);
    } else if (b < 53248) {                // 4 x 1M weights
        const int bb = b - 49152;
        const int t = bb >> 10;
        const int i = ((bb & 1023) << 10) + (threadIdx.x << 2);
        const float* in = (t == 0) ? w0 : (t == 1) ? w1 : (t == 2) ? w2 : w3;
        float4 x = *(const float4*)(in + i);
        __half* d = hw + (t << 20) + i;
        *(__half2*)d = __floats2half2_rn(x.x, x.y);
        *(__half2*)(d + 2) = __floats2half2_rn(x.z, x.w);
    } else {                               // 3 x 1024 biases
        const int idx = ((b - 53248) << 8) + threadIdx.x;   // 0..3071
        const float* s = (idx < 1024) ? b0 : (idx < 2048) ? b1 : b2;
        bias[idx] = s[idx & 1023];
    }
}

// ---------------- softmax over rows of 1024 fp16, in place -------------------
__device__ __forceinline__ float warpMax(float v) {
#pragma unroll
    for (int o = 16; o; o >>= 1) v = fmaxf(v, __shfl_xor_sync(0xffffffffu, v, o));
    return v;
}
__device__ __forceinline__ float warpSum(float v) {
#pragma unroll
    for (int o = 16; o; o >>= 1) v += __shfl_xor_sync(0xffffffffu, v, o);
    return v;
}
__global__ void softmax1024(__half* __restrict__ W) {
    const long long row = blockIdx.x;
    __half2* p = (__half2*)(W + row * 1024);
    const int tid = threadIdx.x;  // 256, 4 halves each
    __half2 h0 = p[2 * tid], h1 = p[2 * tid + 1];
    float2 f0 = __half22float2(h0), f1 = __half22float2(h1);
    float m = fmaxf(fmaxf(f0.x, f0.y), fmaxf(f1.x, f1.y));
    m = warpMax(m);
    __shared__ float sm[8], ss[8];
    if ((tid & 31) == 0) sm[tid >> 5] = m;
    __syncthreads();
    if (tid < 32) {
        float v = (tid < 8) ? sm[tid] : -1e30f;
        v = warpMax(v);
        if (tid == 0) sm[0] = v;
    }
    __syncthreads();
    m = sm[0];
    float e0 = __expf(f0.x - m), e1 = __expf(f0.y - m),
          e2 = __expf(f1.x - m), e3 = __expf(f1.y - m);
    float s = e0 + e1 + e2 + e3;
    s = warpSum(s);
    if ((tid & 31) == 0) ss[tid >> 5] = s;
    __syncthreads();
    if (tid < 32) {
        float v = (tid < 8) ? ss[tid] : 0.f;
        v = warpSum(v);
        if (tid == 0) ss[0] = v;
    }
    __syncthreads();
    const float inv = 1.0f / ss[0];
    p[2 * tid] = __floats2half2_rn(e0 * inv, e1 * inv);
    p[2 * tid + 1] = __floats2half2_rn(e2 * inv, e3 * inv);
}

// ---------------- host side ---------------------------------------------------
extern "C" void kernel_launch(void* const* d_in, const int* in_sizes, int n_in,
                              void* d_out, int out_size) {
    const float* query = (const float*)d_in[0];
    const float* key   = (const float*)d_in[1];
    const float* value = (const float*)d_in[2];
    const float* Wq = (const float*)d_in[3];
    const float* bq = (const float*)d_in[4];
    const float* Wk = (const float*)d_in[5];
    const float* bk = (const float*)d_in[6];
    const float* Wv = (const float*)d_in[7];
    const float* bv = (const float*)d_in[8];
    const float* Wo = (const float*)d_in[9];
    const float* bo = (const float*)d_in[10];
    float* out = (float*)d_out;

    __half *hin, *hw, *q, *k, *v, *w, *o;
    float *bias;
    cudaGetSymbolAddress((void**)&hin, g_in);
    cudaGetSymbolAddress((void**)&hw, g_rw);
    cudaGetSymbolAddress((void**)&bias, g_bias);
    cudaGetSymbolAddress((void**)&q, g_q);
    cudaGetSymbolAddress((void**)&k, g_k);
    cudaGetSymbolAddress((void**)&v, g_v);
    cudaGetSymbolAddress((void**)&w, g_w);
    cudaGetSymbolAddress((void**)&o, g_o);

    cudaFuncSetAttribute(gemm_qkv,
                         cudaFuncAttributeMaxDynamicSharedMemorySize, SMEM_BYTES);
    cudaFuncSetAttribute(gemm_k<false, true>,
                         cudaFuncAttributeMaxDynamicSharedMemorySize, SMEM_BYTES);
    cudaFuncSetAttribute(gemm_k<true, false>,
                         cudaFuncAttributeMaxDynamicSharedMemorySize, SMEM_BYTES);

    prep<<<53260, 256>>>(query, key, value, Wq, Wk, Wv, Wo, bq, bk, bv,
                         hin, hw, bias);

    const long long MB = 1024LL * 1024LL;
    dim3 blk(512);

    // fused q/k/v projections (q,v transposed outputs)
    gemm_qkv<<<dim3(4, 128, 3), blk, SMEM_BYTES>>>(hin, hw, bias, q, k, v);

    // logits: w[b,i,s] = (1/32) sum_t qT[i, b*1024+t] * k[b*1024+s, t]
    gemm_k<false, true><<<dim3(4, 8, 16), blk, SMEM_BYTES>>>(
        q, k, nullptr, w, 1024, MB, MB, 16384, 1024, 1024, 0.03125f);

    softmax1024<<<16 * 1024, 256>>>(w);

    // o[b,i,e] = sum_s a[b,i,s] * vT[e, b*1024+s]
    gemm_k<false, true><<<dim3(4, 8, 16), blk, SMEM_BYTES>>>(
        w, v, nullptr, o, MB, 1024, MB, 1024, 16384, 1024, 1.0f);

    // out = o @ Wo^T + bo  (fp32 output)
    gemm_k<true, false><<<dim3(4, 128, 1), blk, SMEM_BYTES>>>(
        o, hw + 3 * MB, bo, out, 0, 0, 0, 1024, 1024, 1024, 1.0f);
}

// round 17
// speedup vs baseline: 1.1201x; 1.1201x over previous
#include <cuda_runtime.h>
#include <cuda_fp16.h>
#include <cstdint>
#include <math.h>

// ============================================================================
// CustomAttention B=16, T=S=E=1024 fp32 -> FP16 tensor path.
// mma.sync m16n8k16 fp16->fp32, cp.async 3-stage BK=64(halves), ldmatrix,
// all GEMMs K-major (q/v projections store transposed).
// 256-thread CTAs, block 128x128x64, 8 warps of 64x32, 2 CTAs/SM.
// R17 = R16 with the staged-epilogue copy-length bug fixed (8 uint4s, not 4).
// ============================================================================

#define ROWB 144                    // bytes per smem row (72 halves: 64 + 8 pad)
#define AOP_BYTES (128 * ROWB)      // 18432
#define B_OFF_BYTES AOP_BYTES
#define STG_BYTES (2 * AOP_BYTES)   // 36864
#define SMEM_BYTES (3 * STG_BYTES)  // 110592
#define TLD 136                     // transpose-staging row stride (halves)

// ---------------- scratch (device globals; no allocation allowed) -----------
__device__ __half g_in[48u * 1024u * 1024u];  // fp16 query|key|value
__device__ __half g_rw[4u * 1024u * 1024u];   // fp16 Wq|Wk|Wv|Wo
__device__ float  g_bias[3 * 1024];           // bq|bk|bv (fp32)
__device__ __half g_q[16u * 1024u * 1024u];   // qT[i][b*1024+t]  (ld 16384)
__device__ __half g_k[16u * 1024u * 1024u];   // k[b*1024+s][t]   (ld 1024)
__device__ __half g_v[16u * 1024u * 1024u];   // vT[e][b*1024+s]  (ld 16384)
__device__ __half g_w[16u * 1024u * 1024u];
__device__ __half g_o[16u * 1024u * 1024u];

__device__ __forceinline__ void cpa16(uint32_t s, const __half* g) {
    asm volatile("cp.async.cg.shared.global [%0], [%1], 16;" :: "r"(s), "l"(g));
}
#define CP_COMMIT() asm volatile("cp.async.commit_group;")
#define CP_WAIT1()  asm volatile("cp.async.wait_group 1;")

__device__ __forceinline__ void ldsm4(uint32_t* r, uint32_t addr) {
    asm volatile("ldmatrix.sync.aligned.m8n8.x4.shared.b16 {%0,%1,%2,%3}, [%4];"
                 : "=r"(r[0]), "=r"(r[1]), "=r"(r[2]), "=r"(r[3]) : "r"(addr));
}
__device__ __forceinline__ void mma16(float* d, const uint32_t* a,
                                      uint32_t b0, uint32_t b1) {
    asm volatile(
        "mma.sync.aligned.m16n8k16.row.col.f32.f16.f16.f32 "
        "{%0,%1,%2,%3}, {%4,%5,%6,%7}, {%8,%9}, {%0,%1,%2,%3};"
        : "+f"(d[0]), "+f"(d[1]), "+f"(d[2]), "+f"(d[3])
        : "r"(a[0]), "r"(a[1]), "r"(a[2]), "r"(a[3]), "r"(b0), "r"(b1));
}

// ---------------- shared mainloop: 128x128 tile, K=1024 halves, K-major -----
// 256 threads: 8 warps, warp tile 64(M) x 32(N). BK = 64 halves (4 k16 steps).
#define LOAD_A(STGOFF, K16, AA)                                                \
    _Pragma("unroll") for (int mt = 0; mt < 4; mt++)                           \
        ldsm4(AA[mt], aLane + (STGOFF) + mt * (16 * ROWB) + (K16) * 32);

#define LOAD_B(STGOFF, K16, BB)                                                \
    _Pragma("unroll") for (int p = 0; p < 2; p++)                              \
        ldsm4(BB[p], bLane + (STGOFF) + p * (16 * ROWB) + (K16) * 32);

#define DO_MMAS(AA, BB)                                                        \
    _Pragma("unroll") for (int mt = 0; mt < 4; mt++)                           \
        _Pragma("unroll") for (int nt = 0; nt < 4; nt++)                       \
            mma16(acc[mt][nt], AA[mt], BB[nt >> 1][nt & 1],                    \
                  BB[nt >> 1][(nt & 1) + 2]);

// Per k16 section: prefetch next B frags, issue 2 cp.async of next stage,
// run MMAs on current frags, then reload A for the next section.
#define KTILE(CUR, PRE, KT, DOPF)                                              \
    do {                                                                       \
        CP_WAIT1();                                                            \
        __syncthreads();                                                       \
        uint32_t a[4][4], b[2][2][4];                                          \
        LOAD_B((CUR) * STG_BYTES, 0, b[0])                                     \
        LOAD_A((CUR) * STG_BYTES, 0, a)                                        \
        _Pragma("unroll") for (int k16 = 0; k16 < 4; k16++) {                  \
            if (k16 < 3) { LOAD_B((CUR) * STG_BYTES, k16 + 1, b[(k16 + 1) & 1]) } \
            if (DOPF) {                                                        \
                const int k0 = ((KT) + 2) << 6;                                \
                const uint32_t st = (PRE) * STG_BYTES;                         \
                cpa16(saA + st + k16 * (32 * ROWB), gA + k0 + k16 * 32LL * sA); \
                cpa16(saB + st + k16 * (32 * ROWB), gB + k0 + k16 * 32LL * sB); \
            }                                                                  \
            if (k16 == 3) CP_COMMIT();                                         \
            DO_MMAS(a, b[k16 & 1])                                             \
            if (k16 < 3) { LOAD_A((CUR) * STG_BYTES, k16 + 1, a) }             \
        }                                                                      \
    } while (0)

__device__ __forceinline__ void gemm_main(const __half* __restrict__ At,
                                          const __half* __restrict__ Bt,
                                          int sA, int sB, char* smc,
                                          float (&acc)[4][4][4]) {
    const uint32_t smb = (uint32_t)__cvta_generic_to_shared(smc);
    const int tid = threadIdx.x, lane = tid & 31, warp = tid >> 5;
    const int wm = (warp & 1) << 6;        // 0 / 64
    const int wn = (warp >> 1) << 5;       // 0 / 32 / 64 / 96

    // cp.async lanes: row = tid>>3 (+32*i), 16B chunk = (tid&7)*8 halves
    const int rq = tid >> 3, qh = (tid & 7) << 3;
    const __half* gA = At + (long long)rq * sA + qh;
    const __half* gB = Bt + (long long)rq * sB + qh;
    const uint32_t saA = smb + (uint32_t)(rq * ROWB + qh * 2);
    const uint32_t saB = smb + B_OFF_BYTES + (uint32_t)(rq * ROWB + qh * 2);

    // LDSM lane addressing (8x8 b16 matrices)
    const int seg = lane >> 3, li = lane & 7;
    const uint32_t aLane =
        smb + (uint32_t)((wm + ((seg & 1) << 3) + li) * ROWB + ((seg >> 1) << 4));
    const uint32_t bLane =
        smb + B_OFF_BYTES +
        (uint32_t)((wn + ((seg & 1) << 3) + li) * ROWB + ((seg >> 1) << 4));

    // prologue: stages 0,1 (tiles 0,1)
#pragma unroll
    for (int s = 0; s < 2; s++) {
        const uint32_t st = s * STG_BYTES;
        const int k0 = s << 6;
#pragma unroll
        for (int i = 0; i < 4; i++) {
            cpa16(saA + st + i * (32 * ROWB), gA + k0 + i * 32LL * sA);
            cpa16(saB + st + i * (32 * ROWB), gB + k0 + i * 32LL * sB);
        }
        CP_COMMIT();
    }

    // main: 16 k-tiles total; 12 in the 3x-unrolled loop, then 12,13 w/ PF,
    // 14,15 without (empty commits keep the group ledger).
#pragma unroll 1
    for (int kt = 0; kt < 12; kt += 3) {
        KTILE(0, 2, kt, true);
        KTILE(1, 0, kt + 1, true);
        KTILE(2, 1, kt + 2, true);
    }
    KTILE(0, 2, 12, true);
    KTILE(1, 0, 13, true);
    KTILE(2, 1, 14, false);
    KTILE(0, 2, 15, false);
}

// ---------------- standard GEMM: C[z][m][n] = scale*A.B^T (+bias) -----------
// HALFOUT: C is __half (rounded); else C is float with bias added.
template <bool BIAS, bool HALFOUT>
__global__ void __launch_bounds__(256, 2)
gemm_k(const __half* __restrict__ A, const __half* __restrict__ B,
       const float* __restrict__ bias, void* __restrict__ Cv,
       long long bsA, long long bsB, long long bsC,
       int sA, int sB, int ldC, float scale) {
    extern __shared__ char smc[];
    const int bn = blockIdx.x << 7, bm = blockIdx.y << 7, z = blockIdx.z;
    const __half* At = A + (long long)z * bsA + (long long)bm * sA;
    const __half* Bt = B + (long long)z * bsB + (long long)bn * sB;

    float acc[4][4][4];
#pragma unroll
    for (int i = 0; i < 4; i++)
#pragma unroll
        for (int j = 0; j < 4; j++)
#pragma unroll
            for (int l = 0; l < 4; l++) acc[i][j][l] = 0.f;

    gemm_main(At, Bt, sA, sB, smc, acc);

    const int lane = threadIdx.x & 31, warp = threadIdx.x >> 5;
    const int wm = (warp & 1) << 6, wn = (warp >> 1) << 5;
    const int gr = lane >> 2, kr = lane & 3;
#pragma unroll
    for (int mt = 0; mt < 4; mt++) {
        const long long r0 = (long long)(bm + wm + mt * 16 + gr) * ldC;
#pragma unroll
        for (int nt = 0; nt < 4; nt++) {
            const int col = bn + wn + nt * 8 + kr * 2;
            float b0 = 0.f, b1 = 0.f;
            if (BIAS) {
                float2 bb = *(const float2*)(bias + col);
                b0 = bb.x; b1 = bb.y;
            }
            float x0 = acc[mt][nt][0] * scale + b0;
            float x1 = acc[mt][nt][1] * scale + b1;
            float x2 = acc[mt][nt][2] * scale + b0;
            float x3 = acc[mt][nt][3] * scale + b1;
            if (HALFOUT) {
                __half* Cz = (__half*)Cv + (long long)z * bsC;
                *(__half2*)&Cz[r0 + col] = __floats2half2_rn(x0, x1);
                *(__half2*)&Cz[r0 + 8LL * ldC + col] = __floats2half2_rn(x2, x3);
            } else {
                float* Cz = (float*)Cv + (long long)z * bsC;
                *(float2*)&Cz[r0 + col] = make_float2(x0, x1);
                *(float2*)&Cz[r0 + 8LL * ldC + col] = make_float2(x2, x3);
            }
        }
    }
}

// ---------------- fused QKV projection: z=0 qT, z=1 k, z=2 vT ----------------
__global__ void __launch_bounds__(256, 2)
gemm_qkv(const __half* __restrict__ Ain, const __half* __restrict__ W,
         const float* __restrict__ biases,
         __half* __restrict__ Cq, __half* __restrict__ Ck,
         __half* __restrict__ Cv) {
    extern __shared__ char smc[];
    const int bn = blockIdx.x << 7, bm = blockIdx.y << 7, z = blockIdx.z;
    const __half* At = Ain + (long long)z * (16LL << 20) + (long long)bm * 1024;
    const __half* Bt = W + (long long)z * (1LL << 20) + (long long)bn * 1024;
    const float* bias = biases + z * 1024;

    float acc[4][4][4];
#pragma unroll
    for (int i = 0; i < 4; i++)
#pragma unroll
        for (int j = 0; j < 4; j++)
#pragma unroll
            for (int l = 0; l < 4; l++) acc[i][j][l] = 0.f;

    gemm_main(At, Bt, 1024, 1024, smc, acc);

    const int tid = threadIdx.x;
    const int lane = tid & 31, warp = tid >> 5;
    const int wm = (warp & 1) << 6, wn = (warp >> 1) << 5;
    const int gr = lane >> 2, kr = lane & 3;

    if (z == 1) {  // normal store: k[m][n], ld 1024
#pragma unroll
        for (int mt = 0; mt < 4; mt++) {
            const long long r0 = (long long)(bm + wm + mt * 16 + gr) * 1024;
#pragma unroll
            for (int nt = 0; nt < 4; nt++) {
                const int col = bn + wn + nt * 8 + kr * 2;
                float2 bb = *(const float2*)(bias + col);
                *(__half2*)&Ck[r0 + col] =
                    __floats2half2_rn(acc[mt][nt][0] + bb.x, acc[mt][nt][1] + bb.y);
                *(__half2*)&Ck[r0 + 8LL * 1024 + col] =
                    __floats2half2_rn(acc[mt][nt][2] + bb.x, acc[mt][nt][3] + bb.y);
            }
        }
    } else {       // transposed store via smem staging, coalesced 128B writes
        __half* CT = (z == 0) ? Cq : Cv;
        __half* st = (__half*)smc;           // [128 n][TLD m], 34816 B
        __syncthreads();                     // mainloop smem reads done
#pragma unroll
        for (int mt = 0; mt < 4; mt++) {
            const int row = wm + mt * 16 + gr;
#pragma unroll
            for (int nt = 0; nt < 4; nt++) {
                const int col = wn + nt * 8 + kr * 2;
                float2 bb = *(const float2*)(bias + bn + col);
                st[col * TLD + row] = __float2half_rn(acc[mt][nt][0] + bb.x);
                st[(col + 1) * TLD + row] = __float2half_rn(acc[mt][nt][1] + bb.y);
                st[col * TLD + row + 8] = __float2half_rn(acc[mt][nt][2] + bb.x);
                st[(col + 1) * TLD + row + 8] = __float2half_rn(acc[mt][nt][3] + bb.y);
            }
        }
        __syncthreads();
        // 256 threads: n = tid>>1, m-chunk = (tid&1)*64; 64 halves = 8 x 16B
        const int n = tid >> 1, mo = (tid & 1) << 6;
        const uint4* src = (const uint4*)(st + n * TLD + mo);
        uint4* dst = (uint4*)(CT + (long long)(bn + n) * 16384 + bm + mo);
#pragma unroll
        for (int i = 0; i < 8; i++) dst[i] = src[i];
    }
}

// ---------------- prep: fp32 -> fp16 inputs + weights, copy biases ----------
__global__ void prep(const float* __restrict__ q, const float* __restrict__ k,
                     const float* __restrict__ v,
                     const float* __restrict__ w0, const float* __restrict__ w1,
                     const float* __restrict__ w2, const float* __restrict__ w3,
                     const float* __restrict__ b0, const float* __restrict__ b1,
                     const float* __restrict__ b2,
                     __half* __restrict__ hin, __half* __restrict__ hw,
                     float* __restrict__ bias) {
    const int b = blockIdx.x;
    if (b < 49152) {                       // 3 x 16M inputs
        const int t = b >> 14;
        const long long i = ((long long)(b & 16383) << 10) + (threadIdx.x << 2);
        const float* in = (t == 0) ? q : (t == 1) ? k : v;
        float4 x = *(const float4*)(in + i);
        __half* d = hin + (((long long)t) << 24) + i;
        *(__half2*)d = __floats2half2_rn(x.x, x.y);
        *(__half2*)(d + 2) = __floats2half2_rn(x.z, x.w);
    } else if (b < 53248) {                // 4 x 1M weights
        const int bb = b - 49152;
        const int t = bb >> 10;
        const int i = ((bb & 1023) << 10) + (threadIdx.x << 2);
        const float* in = (t == 0) ? w0 : (t == 1) ? w1 : (t == 2) ? w2 : w3;
        float4 x = *(const float4*)(in + i);
        __half* d = hw + (t << 20) + i;
        *(__half2*)d = __floats2half2_rn(x.x, x.y);
        *(__half2*)(d + 2) = __floats2half2_rn(x.z, x.w);
    } else {                               // 3 x 1024 biases
        const int idx = ((b - 53248) << 8) + threadIdx.x;   // 0..3071
        const float* s = (idx < 1024) ? b0 : (idx < 2048) ? b1 : b2;
        bias[idx] = s[idx & 1023];
    }
}

// ---------------- softmax: one warp per row of 1024 fp16, in place ----------
__device__ __forceinline__ float warpMax(float v) {
#pragma unroll
    for (int o = 16; o; o >>= 1) v = fmaxf(v, __shfl_xor_sync(0xffffffffu, v, o));
    return v;
}
__device__ __forceinline__ float warpSum(float v) {
#pragma unroll
    for (int o = 16; o; o >>= 1) v += __shfl_xor_sync(0xffffffffu, v, o);
    return v;
}
__global__ void softmax1024(__half* __restrict__ W) {
    const int lane = threadIdx.x & 31;
    const long long row = (long long)blockIdx.x * 4 + (threadIdx.x >> 5);
    uint4* p = (uint4*)(W + row * 1024) + lane;   // 8 halves per uint4, x4

    uint4 u[4];
    float f[32];
#pragma unroll
    for (int i = 0; i < 4; i++) u[i] = p[i * 32];
#pragma unroll
    for (int i = 0; i < 4; i++) {
        const __half2* h = (const __half2*)&u[i];
#pragma unroll
        for (int j = 0; j < 4; j++) {
            float2 fj = __half22float2(h[j]);
            f[i * 8 + j * 2] = fj.x;
            f[i * 8 + j * 2 + 1] = fj.y;
        }
    }
    float m = -1e30f;
#pragma unroll
    for (int i = 0; i < 32; i++) m = fmaxf(m, f[i]);
    m = warpMax(m);
    float s = 0.f;
#pragma unroll
    for (int i = 0; i < 32; i++) { f[i] = __expf(f[i] - m); s += f[i]; }
    s = warpSum(s);
    const float inv = 1.0f / s;
#pragma unroll
    for (int i = 0; i < 4; i++) {
        __half2* h = (__half2*)&u[i];
#pragma unroll
        for (int j = 0; j < 4; j++)
            h[j] = __floats2half2_rn(f[i * 8 + j * 2] * inv,
                                     f[i * 8 + j * 2 + 1] * inv);
    }
#pragma unroll
    for (int i = 0; i < 4; i++) p[i * 32] = u[i];
}

// ---------------- host side ---------------------------------------------------
extern "C" void kernel_launch(void* const* d_in, const int* in_sizes, int n_in,
                              void* d_out, int out_size) {
    const float* query = (const float*)d_in[0];
    const float* key   = (const float*)d_in[1];
    const float* value = (const float*)d_in[2];
    const float* Wq = (const float*)d_in[3];
    const float* bq = (const float*)d_in[4];
    const float* Wk = (const float*)d_in[5];
    const float* bk = (const float*)d_in[6];
    const float* Wv = (const float*)d_in[7];
    const float* bv = (const float*)d_in[8];
    const float* Wo = (const float*)d_in[9];
    const float* bo = (const float*)d_in[10];
    float* out = (float*)d_out;

    __half *hin, *hw, *q, *k, *v, *w, *o;
    float *bias;
    cudaGetSymbolAddress((void**)&hin, g_in);
    cudaGetSymbolAddress((void**)&hw, g_rw);
    cudaGetSymbolAddress((void**)&bias, g_bias);
    cudaGetSymbolAddress((void**)&q, g_q);
    cudaGetSymbolAddress((void**)&k, g_k);
    cudaGetSymbolAddress((void**)&v, g_v);
    cudaGetSymbolAddress((void**)&w, g_w);
    cudaGetSymbolAddress((void**)&o, g_o);

    cudaFuncSetAttribute(gemm_qkv,
                         cudaFuncAttributeMaxDynamicSharedMemorySize, SMEM_BYTES);
    cudaFuncSetAttribute(gemm_k<false, true>,
                         cudaFuncAttributeMaxDynamicSharedMemorySize, SMEM_BYTES);
    cudaFuncSetAttribute(gemm_k<true, false>,
                         cudaFuncAttributeMaxDynamicSharedMemorySize, SMEM_BYTES);

    prep<<<53260, 256>>>(query, key, value, Wq, Wk, Wv, Wo, bq, bk, bv,
                         hin, hw, bias);

    const long long MB = 1024LL * 1024LL;
    dim3 blk(256);

    // fused q/k/v projections (q,v transposed outputs)
    gemm_qkv<<<dim3(8, 128, 3), blk, SMEM_BYTES>>>(hin, hw, bias, q, k, v);

    // logits: w[b,i,s] = (1/32) sum_t qT[i, b*1024+t] * k[b*1024+s, t]
    gemm_k<false, true><<<dim3(8, 8, 16), blk, SMEM_BYTES>>>(
        q, k, nullptr, w, 1024, MB, MB, 16384, 1024, 1024, 0.03125f);

    softmax1024<<<4096, 128>>>(w);

    // o[b,i,e] = sum_s a[b,i,s] * vT[e, b*1024+s]
    gemm_k<false, true><<<dim3(8, 8, 16), blk, SMEM_BYTES>>>(
        w, v, nullptr, o, MB, 1024, MB, 1024, 16384, 1024, 1.0f);

    // out = o @ Wo^T + bo  (fp32 output)
    gemm_k<true, false><<<dim3(8, 128, 1), blk, SMEM_BYTES>>>(
        o, hw + 3 * MB, bo, out, 0, 0, 0, 1024, 1024, 1024, 1.0f);
}